// round 4
// baseline (speedup 1.0000x reference)
#include <cuda_runtime.h>
#include <cuda_bf16.h>

#define NTS   2048
#define KXV   256
#define NYV   8192
#define NTH   1024
#define VPT   8      // Y vars per thread (8192/1024)

__global__ __launch_bounds__(NTH, 1)
void lorenz96_kernel(const float* __restrict__ X0,
                     const float* __restrict__ Y0,
                     const float* __restrict__ coupling,
                     const float* __restrict__ pF,
                     const float* __restrict__ ph,
                     const float* __restrict__ pc,
                     const float* __restrict__ pdt,
                     float* __restrict__ xhist,
                     float* __restrict__ yhist)
{
    // double-buffered stage values: full X vector + Y halo edges only
    __shared__ float sX[2][KXV];
    __shared__ float e0[2][NTH];   // each thread's Y var 0 (left edge)
    __shared__ float e1[2][NTH];   // var 1
    __shared__ float e7[2][NTH];   // var 7 (right edge)

    const int t = threadIdx.x;
    const bool isX = (t < KXV);

    const float F  = *pF;
    const float h  = *ph;
    const float c  = *pc;
    const float dt = *pdt;

    // scalar constants exactly as the reference forms them (all exact here)
    const float a      = __fmul_rn(__fmul_rn(-1.0f, c), 32.0f);           // (-c)*J
    const float hcJ    = __fdiv_rn(__fmul_rn(h, c), 32.0f);               // (h*c)/J
    const float halfdt = __fmul_rn(0.5f, dt);                             // 0.5*dt
    const float dt6    = __fdiv_rn(dt, 6.0f);                             // dt/6.0

    const int j0 = t * VPT;
    const int xi = t >> 2;                 // X index feeding this thread's 8 Y vars

    float yb[VPT], yc[VPT], d1[VPT], d2[VPT];

    // ---- init from row 0 of X0 / Y0 ----
    #pragma unroll
    for (int v = 0; v < VPT; v += 4) {
        float4 q = *reinterpret_cast<const float4*>(Y0 + j0 + v);
        yb[v] = q.x; yb[v+1] = q.y; yb[v+2] = q.z; yb[v+3] = q.w;
    }
    #pragma unroll
    for (int v = 0; v < VPT; v++) yc[v] = yb[v];

    // row 0 outputs are the initial conditions
    #pragma unroll
    for (int v = 0; v < VPT; v += 4) {
        float4 q; q.x = yb[v]; q.y = yb[v+1]; q.z = yb[v+2]; q.w = yb[v+3];
        *reinterpret_cast<float4*>(yhist + j0 + v) = q;
    }

    float xb = 0.f, xc = 0.f, xd1 = 0.f, xd2 = 0.f;
    float coup_next = 0.f;
    if (isX) {
        xb = X0[t];
        xc = xb;
        xhist[t] = xb;
        sX[0][t] = xb;
        coup_next = coupling[t];           // coupling row 0 drives step n=1
    }
    e0[0][t] = yc[0];
    e1[0][t] = yc[1];
    e7[0][t] = yc[7];
    __syncthreads();

    const int tl = (t + NTH - 1) & (NTH - 1);
    const int tr = (t + 1) & (NTH - 1);

    for (int n = 1; n < NTS; n++) {
        const float coup = coup_next;
        if (isX && n < NTS - 1) coup_next = coupling[n * KXV + t];  // prefetch next step

        #pragma unroll
        for (int s = 0; s < 4; s++) {
            const int rb = s & 1;          // s0 reads buf0 (state), s1 buf1, s2 buf0, s3 buf1
            const int wb = rb ^ 1;

            // halos from neighbor threads (stage values)
            const float left = e7[rb][tl];     // Y[j0-1]
            const float r0p  = e0[rb][tr];     // Y[j0+8]
            const float r1p  = e1[rb][tr];     // Y[j0+9]
            const float xs   = sX[rb][xi];

            float dn[VPT];
            #pragma unroll
            for (int v = 0; v < VPT; v++) {
                const float ym1 = (v == 0)       ? left : yc[v-1];
                const float yp1 = (v == VPT-1)   ? r0p  : yc[v+1];
                const float yp2 = (v == VPT-2)   ? r0p  :
                                  ((v == VPT-1)  ? r1p  : yc[v+2]);
                // LLVM-style contraction of:
                //   ((a*Y[j+1]) * (Y[j+2]-Y[j-1])) - (c*Y[j]) + (hcJ*X)
                //   fsub(fmul,fmul) -> fma(first_mul, -(second_mul))
                //   fadd(fma, fmul) -> fma(hcJ, X, prev)
                const float t1 = __fsub_rn(yp2, ym1);
                const float t2 = __fmul_rn(a, yp1);
                const float t4 = __fmul_rn(c, yc[v]);
                const float t5 = __fmaf_rn(t2, t1, -t4);
                dn[v] = __fmaf_rn(hcJ, xs, t5);
            }

            float xdn = 0.f;
            if (isX) {
                const float xm2 = sX[rb][(t + KXV - 2) & (KXV - 1)];
                const float xm1 = sX[rb][(t + KXV - 1) & (KXV - 1)];
                const float xp1 = sX[rb][(t + 1) & (KXV - 1)];
                // ((fma(X[k-1], (X[k+1]-X[k-2]), -X[k])) + F) + coup
                const float u1 = __fsub_rn(xp1, xm2);
                const float u3 = __fmaf_rn(xm1, u1, -xc);
                const float u4 = __fadd_rn(u3, F);
                xdn = __fadd_rn(u4, coup);
            }

            if (s == 0) {
                #pragma unroll
                for (int v = 0; v < VPT; v++) {
                    d1[v] = dn[v];
                    yc[v] = __fmaf_rn(halfdt, dn[v], yb[v]);
                }
                if (isX) { xd1 = xdn; xc = __fmaf_rn(halfdt, xdn, xb); }
            } else if (s == 1) {
                #pragma unroll
                for (int v = 0; v < VPT; v++) {
                    d2[v] = dn[v];
                    yc[v] = __fmaf_rn(halfdt, dn[v], yb[v]);
                }
                if (isX) { xd2 = xdn; xc = __fmaf_rn(halfdt, xdn, xb); }
            } else if (s == 2) {
                #pragma unroll
                for (int v = 0; v < VPT; v++) {
                    d2[v] = __fadd_rn(d2[v], dn[v]);                  // d2+d3 (plain add)
                    yc[v] = __fmaf_rn(dt, dn[v], yb[v]);
                }
                if (isX) { xd2 = __fadd_rn(xd2, xdn); xc = __fmaf_rn(dt, xdn, xb); }
            } else {
                #pragma unroll
                for (int v = 0; v < VPT; v++) {
                    // sum = fma(2.0, (d2+d3), (d1+d4)); new = fma(dt/6, sum, base)
                    const float sA  = __fadd_rn(d1[v], dn[v]);
                    const float sum = __fmaf_rn(2.0f, d2[v], sA);
                    const float yn  = __fmaf_rn(dt6, sum, yb[v]);
                    yb[v] = yn; yc[v] = yn;
                }
                if (isX) {
                    const float sA  = __fadd_rn(xd1, xdn);
                    const float sum = __fmaf_rn(2.0f, xd2, sA);
                    const float xn  = __fmaf_rn(dt6, sum, xb);
                    xb = xn; xc = xn;
                }
            }

            // publish next-stage boundary values
            e0[wb][t] = yc[0];
            e1[wb][t] = yc[1];
            e7[wb][t] = yc[7];
            if (isX) sX[wb][t] = xc;
            __syncthreads();
        }

        // write history row n (fire-and-forget STG)
        float* yrow = yhist + (size_t)n * NYV + j0;
        #pragma unroll
        for (int v = 0; v < VPT; v += 4) {
            float4 q; q.x = yc[v]; q.y = yc[v+1]; q.z = yc[v+2]; q.w = yc[v+3];
            *reinterpret_cast<float4*>(yrow + v) = q;
        }
        if (isX) xhist[(size_t)n * KXV + t] = xc;
    }
}

extern "C" void kernel_launch(void* const* d_in, const int* in_sizes, int n_in,
                              void* d_out, int out_size)
{
    const float* X0 = (const float*)d_in[0];
    const float* Y0 = (const float*)d_in[1];
    const float* cp = (const float*)d_in[2];
    const float* pF = (const float*)d_in[3];
    const float* ph = (const float*)d_in[4];
    // d_in[5] = b (unused by the math)
    const float* pc = (const float*)d_in[6];
    const float* pdt = (const float*)d_in[7];

    float* out   = (float*)d_out;
    float* xhist = out;                       // [2048, 256]
    float* yhist = out + (size_t)NTS * KXV;   // [2048, 8192]

    lorenz96_kernel<<<1, NTH>>>(X0, Y0, cp, pF, ph, pc, pdt, xhist, yhist);
}